// round 14
// baseline (speedup 1.0000x reference)
#include <cuda_runtime.h>
#include <cstdint>

#define NA 8192
#define NN 65536
#define NE 262144
#define D  128
#define NB 2
#define MT  128          // rows per HMMA CTA
#define NT  512          // threads per CTA (16 warps)
#define SA  68           // smem pair stride (64 pairs + 4 pad -> conflict-free)
#define EPS 1e-5f

// ---------------- scratch (device globals; no allocation allowed) ------------
__device__ float g_q [NA * D];   // relu(GN(actors @ Wq^T))
__device__ float g_qw[NA * D];   // g_q @ Wc0[:,128:256]^T
__device__ float g_cw[NN * D];   // nodes @ Wc0[:,256:384]^T
__device__ float g_a [NA * D];   // actors @ Wagt^T (+ scattered messages)
__device__ float g_x [NA * D];
__device__ float g_act[NA * D];

// ----------------------------- bf16 helpers ----------------------------------
__device__ __forceinline__ uint32_t pk(float e, float o) {
    uint32_t r;
    asm("cvt.rn.bf16x2.f32 %0, %1, %2;" : "=r"(r) : "f"(o), "f"(e));
    return r;  // lo16 = e (even k), hi16 = o (odd k)
}
__device__ __forceinline__ float lo16f(uint32_t p) { return __uint_as_float(p << 16); }
__device__ __forceinline__ float hi16f(uint32_t p) { return __uint_as_float(p & 0xffff0000u); }

__device__ __forceinline__ uint32_t su32(const void* p) {
    uint32_t a;
    asm("{ .reg .u64 t; cvta.to.shared.u64 t, %1; cvt.u32.u64 %0, t; }"
        : "=r"(a) : "l"(p));
    return a;
}

__device__ __forceinline__ void mma16816(float* c,
                                         const uint32_t* a,
                                         uint32_t b0, uint32_t b1) {
    asm volatile(
        "mma.sync.aligned.m16n8k16.row.col.f32.bf16.bf16.f32 "
        "{%0,%1,%2,%3}, {%4,%5,%6,%7}, {%8,%9}, {%0,%1,%2,%3};"
        : "+f"(c[0]), "+f"(c[1]), "+f"(c[2]), "+f"(c[3])
        : "r"(a[0]), "r"(a[1]), "r"(a[2]), "r"(a[3]), "r"(b0), "r"(b1));
}

__device__ __forceinline__ void ldm4(uint32_t* r, uint32_t a) {
    asm volatile("ldmatrix.sync.aligned.m8n8.x4.shared.b16 {%0,%1,%2,%3}, [%4];"
                 : "=r"(r[0]), "=r"(r[1]), "=r"(r[2]), "=r"(r[3]) : "r"(a));
}

// stage one [128 x 128] fp32 matrix chunk -> bf16 hi/lo pair buffers (512 thr)
__device__ __forceinline__ void stageB(const float* __restrict__ W, int rowlen,
                                       uint32_t* __restrict__ Bh,
                                       uint32_t* __restrict__ Bl) {
    const int t = threadIdx.x;
    const int n = t >> 2, kq = (t & 3) << 5;   // 32 floats per thread
    const float4* src = reinterpret_cast<const float4*>(W + (size_t)n * rowlen + kq);
    const int pb = n * SA + ((t & 3) << 4);
#pragma unroll
    for (int i = 0; i < 8; i++) {
        float4 v = src[i];
        uint32_t h0 = pk(v.x, v.y), h1 = pk(v.z, v.w);
        Bh[pb + 2 * i]     = h0;
        Bh[pb + 2 * i + 1] = h1;
        Bl[pb + 2 * i]     = pk(v.x - lo16f(h0), v.y - hi16f(h0));
        Bl[pb + 2 * i + 1] = pk(v.z - lo16f(h1), v.w - hi16f(h1));
    }
}

// 3-term emulated fp32 GEMM via ldmatrix, 16 warps:
// warp (wM 0..7, wN 0..1): rows wM*16..+15 (1 m-tile), cols wN*64..+63.
// B fragment loads pipelined one j-iteration ahead.
__device__ __forceinline__ void do_gemm(
    const uint32_t* Ah, const uint32_t* Al,
    const uint32_t* Bh, const uint32_t* Bl,
    int wM, int wN, int lane, float (&c)[8][4]) {
    const int lr = lane & 15;
    const uint32_t khA = (uint32_t)((lane >> 4) << 4);
    uint32_t aHi = su32(Ah) + (uint32_t)((wM * 16 + lr) * SA * 4) + khA;
    uint32_t aLo = su32(Al) + (uint32_t)((wM * 16 + lr) * SA * 4) + khA;
    const int bn = (lane & 7) + ((lane >> 4) << 3);
    const uint32_t khB = (uint32_t)(((lane >> 3) & 1) << 4);
    uint32_t bHi = su32(Bh) + (uint32_t)((wN * 64 + bn) * SA * 4) + khB;
    uint32_t bLo = su32(Bl) + (uint32_t)((wN * 64 + bn) * SA * 4) + khB;

    for (int s = 0; s < 8; s++) {
        const uint32_t off = (uint32_t)(s * 32);  // 8 k-pairs = 32 bytes
        uint32_t ah[4], al[4];
        ldm4(ah, aHi + off);
        ldm4(al, aLo + off);
        uint32_t bh[4], bl[4], bh2[4], bl2[4];
        ldm4(bh, bHi + off);
        ldm4(bl, bLo + off);
#pragma unroll
        for (int j = 0; j < 4; j++) {
            if (j < 3) {
                ldm4(bh2, bHi + off + (uint32_t)((j + 1) * 16 * SA * 4));
                ldm4(bl2, bLo + off + (uint32_t)((j + 1) * 16 * SA * 4));
            }
            const int n0 = 2 * j, n1 = 2 * j + 1;
            mma16816(c[n0], al, bh[0], bh[1]);
            mma16816(c[n0], ah, bl[0], bl[1]);
            mma16816(c[n0], ah, bh[0], bh[1]);
            mma16816(c[n1], al, bh[2], bh[3]);
            mma16816(c[n1], ah, bl[2], bl[3]);
            mma16816(c[n1], ah, bh[2], bh[3]);
            if (j < 3) {
#pragma unroll
                for (int t = 0; t < 4; t++) { bh[t] = bh2[t]; bl[t] = bl2[t]; }
            }
        }
    }
}

// GN(+relu) epilogue over C; writes normalized bf16 hi/lo back to A pairs 0..63
__device__ __forceinline__ void epi_gn(
    float (&c)[8][4], const float* __restrict__ sG, const float* __restrict__ sB,
    uint32_t* __restrict__ Ah, uint32_t* __restrict__ Al,
    float (*sSum)[MT], float (*sSq)[MT], int wM, int wN, int g, int tq) {
    float s_[2] = {0, 0}, q_[2] = {0, 0};
#pragma unroll
    for (int nf = 0; nf < 8; nf++) {
        float v0 = c[nf][0], v1 = c[nf][1];
        float v2 = c[nf][2], v3 = c[nf][3];
        s_[0] += v0 + v1;
        q_[0] = fmaf(v0, v0, fmaf(v1, v1, q_[0]));
        s_[1] += v2 + v3;
        q_[1] = fmaf(v2, v2, fmaf(v3, v3, q_[1]));
    }
#pragma unroll
    for (int h = 0; h < 2; h++) {
        s_[h] += __shfl_xor_sync(0xffffffffu, s_[h], 1);
        s_[h] += __shfl_xor_sync(0xffffffffu, s_[h], 2);
        q_[h] += __shfl_xor_sync(0xffffffffu, q_[h], 1);
        q_[h] += __shfl_xor_sync(0xffffffffu, q_[h], 2);
    }
    if (tq == 0) {
#pragma unroll
        for (int h = 0; h < 2; h++) {
            int row = wM * 16 + g + 8 * h;
            sSum[wN][row] = s_[h];
            sSq[wN][row]  = q_[h];
        }
    }
    __syncthreads();
    float mu[2], rs[2];
#pragma unroll
    for (int h = 0; h < 2; h++) {
        int row = wM * 16 + g + 8 * h;
        float S = sSum[0][row] + sSum[1][row];
        float Q = sSq[0][row] + sSq[1][row];
        mu[h] = S * (1.0f / 128.0f);
        rs[h] = rsqrtf(Q * (1.0f / 128.0f) - mu[h] * mu[h] + EPS);
    }
    const int rb = wM * 16 + g;
#pragma unroll
    for (int nf = 0; nf < 8; nf++) {
        const int ch = wN * 64 + nf * 8 + 2 * tq;
        const float g0 = sG[ch], g1 = sG[ch + 1];
        const float b0 = sB[ch], b1 = sB[ch + 1];
        const int p = wN * 32 + nf * 4 + tq;
        float e = fmaxf((c[nf][0] - mu[0]) * rs[0] * g0 + b0, 0.0f);
        float o = fmaxf((c[nf][1] - mu[0]) * rs[0] * g1 + b1, 0.0f);
        uint32_t hp = pk(e, o);
        Ah[rb * SA + p] = hp;
        Al[rb * SA + p] = pk(e - lo16f(hp), o - hi16f(hp));
        e = fmaxf((c[nf][2] - mu[1]) * rs[1] * g0 + b0, 0.0f);
        o = fmaxf((c[nf][3] - mu[1]) * rs[1] * g1 + b1, 0.0f);
        hp = pk(e, o);
        Ah[(rb + 8) * SA + p] = hp;
        Al[(rb + 8) * SA + p] = pk(e - lo16f(hp), o - hi16f(hp));
    }
}

// ============================ edge kernel (HMMA) =============================
__global__ void __launch_bounds__(NT, 1) edge_mma_kernel(
    const float* __restrict__ actor_ctrs, const float* __restrict__ node_ctrs,
    const int* __restrict__ hi, const int* __restrict__ wi,
    const float* __restrict__ W0, const float* __restrict__ b0,
    const float* __restrict__ W1, const float* __restrict__ g1, const float* __restrict__ b1v,
    const float* __restrict__ Wc0d, const float* __restrict__ gc0, const float* __restrict__ bc0,
    const float* __restrict__ Wc1) {
    extern __shared__ uint32_t smu[];
    uint32_t* Ah = smu;
    uint32_t* Al = smu + 128 * SA;
    uint32_t* Bh = smu + 2 * 128 * SA;
    uint32_t* Bl = smu + 3 * 128 * SA;
    __shared__ float sW0[2 * D], sB0[D], sG1[D], sB1[D], sGc[D], sBc[D];
    __shared__ int sHi[MT], sWi[MT];
    __shared__ float sSum[2][MT], sSq[2][MT];

    const int tid = threadIdx.x;
    const int lane = tid & 31, wid = tid >> 5;
    const int wN = wid & 1, wM = wid >> 1;          // wM 0..7
    const int g = lane >> 2, tq = lane & 3;
    const int e0 = blockIdx.x * MT;

    if (tid < 2 * D) sW0[tid] = W0[tid];
    if (tid < D) {
        sB0[tid] = b0[tid]; sG1[tid] = g1[tid]; sB1[tid] = b1v[tid];
        sGc[tid] = gc0[tid]; sBc[tid] = bc0[tid];
        sHi[tid] = hi[e0 + tid]; sWi[tid] = wi[e0 + tid];
    }
    __syncthreads();

    // ---- phase 0: h -> A pairs 0..63 ; stage B = W1 ----
    {
        const int row = tid >> 2, qf = tid & 3;    // 16 pairs per thread
        const int h_ = sHi[row], w_ = sWi[row];
        float2 ac = reinterpret_cast<const float2*>(actor_ctrs)[h_];
        float2 nc = reinterpret_cast<const float2*>(node_ctrs)[w_];
        float dx = ac.x - nc.x, dy = ac.y - nc.y;
#pragma unroll
        for (int i = 0; i < 16; i++) {
            int ch = qf * 32 + 2 * i;
            float e = fmaxf(fmaf(dx, sW0[2 * ch],     fmaf(dy, sW0[2 * ch + 1], sB0[ch])),     0.0f);
            float o = fmaxf(fmaf(dx, sW0[2 * ch + 2], fmaf(dy, sW0[2 * ch + 3], sB0[ch + 1])), 0.0f);
            uint32_t hp = pk(e, o);
            Ah[row * SA + qf * 16 + i] = hp;
            Al[row * SA + qf * 16 + i] = pk(e - lo16f(hp), o - hi16f(hp));
        }
    }
    stageB(W1, 128, Bh, Bl);
    __syncthreads();

    float c[8][4];

    // ---- GEMM1: d_pre = h @ W1^T ----
#pragma unroll
    for (int nf = 0; nf < 8; nf++)
#pragma unroll
        for (int j = 0; j < 4; j++) c[nf][j] = 0.0f;
    do_gemm(Ah, Al, Bh, Bl, wM, wN, lane, c);
    epi_gn(c, sG1, sB1, Ah, Al, sSum, sSq, wM, wN, g, tq);
    stageB(Wc0d, 384, Bh, Bl);
    __syncthreads();

    // ---- GEMM2: u_pre = d @ Wc0d^T + qW[hi] + cW[wi] ----
#pragma unroll
    for (int h = 0; h < 2; h++) {
        int row = wM * 16 + g + 8 * h;
        const float2* qp = reinterpret_cast<const float2*>(
            g_qw + (size_t)sHi[row] * D + wN * 64);
        const float2* cp = reinterpret_cast<const float2*>(
            g_cw + (size_t)sWi[row] * D + wN * 64);
#pragma unroll
        for (int nf = 0; nf < 8; nf++) {
            float2 a_ = qp[nf * 4 + tq];
            float2 b_ = cp[nf * 4 + tq];
            c[nf][2 * h]     = a_.x + b_.x;
            c[nf][2 * h + 1] = a_.y + b_.y;
        }
    }
    do_gemm(Ah, Al, Bh, Bl, wM, wN, lane, c);
    epi_gn(c, sGc, sBc, Ah, Al, sSum, sSq, wM, wN, g, tq);
    stageB(Wc1, 128, Bh, Bl);
    __syncthreads();

    // ---- GEMM3: m = u @ Wc1^T ; scatter ----
#pragma unroll
    for (int nf = 0; nf < 8; nf++)
#pragma unroll
        for (int j = 0; j < 4; j++) c[nf][j] = 0.0f;
    do_gemm(Ah, Al, Bh, Bl, wM, wN, lane, c);
#pragma unroll
    for (int h = 0; h < 2; h++) {
        int row = wM * 16 + g + 8 * h;
        float* base = g_a + (size_t)sHi[row] * D + wN * 64;
#pragma unroll
        for (int nf = 0; nf < 8; nf++) {
            int ch = nf * 8 + 2 * tq;
            atomicAdd(base + ch,     c[nf][2 * h]);
            atomicAdd(base + ch + 1, c[nf][2 * h + 1]);
        }
    }
}

// ================= HMMA row-GEMM: out[128,128] = f(in @ W^T) =================
template <bool GN, bool RELU, bool RES>
__global__ void __launch_bounds__(NT, 1) hgemm_kernel(
    const float* __restrict__ in, const float* __restrict__ W, int wstride,
    const float* __restrict__ gw, const float* __restrict__ bw,
    const float* __restrict__ res, float* __restrict__ out) {
    extern __shared__ uint32_t smu[];
    uint32_t* Ah = smu;
    uint32_t* Al = smu + 128 * SA;
    uint32_t* Bh = smu + 2 * 128 * SA;
    uint32_t* Bl = smu + 3 * 128 * SA;
    __shared__ float sG[D], sB[D];
    __shared__ float sSum[2][MT], sSq[2][MT];

    const int tid = threadIdx.x;
    const int lane = tid & 31, wid = tid >> 5;
    const int wN = wid & 1, wM = wid >> 1;
    const int g = lane >> 2, tq = lane & 3;
    const size_t r0 = (size_t)blockIdx.x * MT;

    if (GN && tid < D) { sG[tid] = gw[tid]; sB[tid] = bw[tid]; }
    stageB(in + r0 * D, 128, Ah, Al);
    stageB(W, wstride, Bh, Bl);
    __syncthreads();

    float c[8][4];
#pragma unroll
    for (int nf = 0; nf < 8; nf++)
#pragma unroll
        for (int j = 0; j < 4; j++) c[nf][j] = 0.0f;
    do_gemm(Ah, Al, Bh, Bl, wM, wN, lane, c);

    if (GN) {
        float s_[2] = {0, 0}, q_[2] = {0, 0};
#pragma unroll
        for (int nf = 0; nf < 8; nf++) {
            float v0 = c[nf][0], v1 = c[nf][1];
            float v2 = c[nf][2], v3 = c[nf][3];
            s_[0] += v0 + v1;
            q_[0] = fmaf(v0, v0, fmaf(v1, v1, q_[0]));
            s_[1] += v2 + v3;
            q_[1] = fmaf(v2, v2, fmaf(v3, v3, q_[1]));
        }
#pragma unroll
        for (int h = 0; h < 2; h++) {
            s_[h] += __shfl_xor_sync(0xffffffffu, s_[h], 1);
            s_[h] += __shfl_xor_sync(0xffffffffu, s_[h], 2);
            q_[h] += __shfl_xor_sync(0xffffffffu, q_[h], 1);
            q_[h] += __shfl_xor_sync(0xffffffffu, q_[h], 2);
        }
        if (tq == 0) {
#pragma unroll
            for (int h = 0; h < 2; h++) {
                int row = wM * 16 + g + 8 * h;
                sSum[wN][row] = s_[h];
                sSq[wN][row]  = q_[h];
            }
        }
        __syncthreads();
#pragma unroll
        for (int h = 0; h < 2; h++) {
            int row = wM * 16 + g + 8 * h;
            float S = sSum[0][row] + sSum[1][row];
            float Q = sSq[0][row] + sSq[1][row];
            float mu = S * (1.0f / 128.0f);
            float rs = rsqrtf(Q * (1.0f / 128.0f) - mu * mu + EPS);
            float* op = out + (r0 + row) * D;
            const float* rp = RES ? res + (r0 + row) * D : nullptr;
#pragma unroll
            for (int nf = 0; nf < 8; nf++) {
                int ch = wN * 64 + nf * 8 + 2 * tq;
                float y0 = (c[nf][2 * h]     - mu) * rs * sG[ch]     + sB[ch];
                float y1 = (c[nf][2 * h + 1] - mu) * rs * sG[ch + 1] + sB[ch + 1];
                if (RES) { y0 += rp[ch]; y1 += rp[ch + 1]; }
                if (RELU) { y0 = fmaxf(y0, 0.0f); y1 = fmaxf(y1, 0.0f); }
                *reinterpret_cast<float2*>(op + ch) = make_float2(y0, y1);
            }
        }
    } else {
#pragma unroll
        for (int h = 0; h < 2; h++) {
            int row = wM * 16 + g + 8 * h;
            float* op = out + (r0 + row) * D;
#pragma unroll
            for (int nf = 0; nf < 8; nf++) {
                int ch = wN * 64 + nf * 8 + 2 * tq;
                float y0 = c[nf][2 * h], y1 = c[nf][2 * h + 1];
                if (RELU) { y0 = fmaxf(y0, 0.0f); y1 = fmaxf(y1, 0.0f); }
                *reinterpret_cast<float2*>(op + ch) = make_float2(y0, y1);
            }
        }
    }
}

// x = relu(GN(a)) ; one warp per row
__global__ void __launch_bounds__(256) gnrows_kernel(
    const float* __restrict__ in, const float* __restrict__ g,
    const float* __restrict__ bb, float* __restrict__ out) {
    const int lane = threadIdx.x & 31;
    const int row = blockIdx.x * 8 + (threadIdx.x >> 5);
    const float* x = in + (size_t)row * D;
    float v0 = x[lane], v1 = x[lane + 32], v2 = x[lane + 64], v3 = x[lane + 96];
    float s = v0 + v1 + v2 + v3;
    float q = fmaf(v0, v0, fmaf(v1, v1, fmaf(v2, v2, v3 * v3)));
#pragma unroll
    for (int o = 16; o > 0; o >>= 1) {
        s += __shfl_xor_sync(0xffffffffu, s, o);
        q += __shfl_xor_sync(0xffffffffu, q, o);
    }
    float mu = s * (1.0f / 128.0f);
    float rs = rsqrtf(q * (1.0f / 128.0f) - mu * mu + EPS);
    float* o_ = out + (size_t)row * D;
    o_[lane]      = fmaxf((v0 - mu) * rs * g[lane] + bb[lane], 0.0f);
    o_[lane + 32] = fmaxf((v1 - mu) * rs * g[lane + 32] + bb[lane + 32], 0.0f);
    o_[lane + 64] = fmaxf((v2 - mu) * rs * g[lane + 64] + bb[lane + 64], 0.0f);
    o_[lane + 96] = fmaxf((v3 - mu) * rs * g[lane + 96] + bb[lane + 96], 0.0f);
}

#define EDGE_SMEM (4 * 128 * SA * 4)

extern "C" void kernel_launch(void* const* d_in, const int* in_sizes, int n_in,
                              void* d_out, int out_size) {
    (void)in_sizes; (void)n_in; (void)out_size;
    const float* actors     = (const float*)d_in[0];
    const float* nodes      = (const float*)d_in[1];
    const float* actor_ctrs = (const float*)d_in[2];
    const float* node_ctrs  = (const float*)d_in[3];
    const int*   hi         = (const int*)d_in[4];
    const int*   wi         = (const int*)d_in[5];
    const float* dist0_W = (const float*)d_in[6];
    const float* dist0_b = (const float*)d_in[7];
    const float* dist1_W = (const float*)d_in[8];
    const float* dist1_g = (const float*)d_in[9];
    const float* dist1_b = (const float*)d_in[10];
    const float* query_W = (const float*)d_in[11];
    const float* query_g = (const float*)d_in[12];
    const float* query_b = (const float*)d_in[13];
    const float* ctx0_W  = (const float*)d_in[14];
    const float* ctx0_g  = (const float*)d_in[15];
    const float* ctx0_b  = (const float*)d_in[16];
    const float* ctx1_W  = (const float*)d_in[17];
    const float* agt_W   = (const float*)d_in[18];
    const float* norm_g  = (const float*)d_in[19];
    const float* norm_b  = (const float*)d_in[20];
    const float* lin_W   = (const float*)d_in[21];
    const float* lin_g   = (const float*)d_in[22];
    const float* lin_b   = (const float*)d_in[23];
    float* outp = (float*)d_out;

    void *pq_, *pqw_, *pcw_, *pa_, *px_, *pact_;
    cudaGetSymbolAddress(&pq_, g_q);
    cudaGetSymbolAddress(&pqw_, g_qw);
    cudaGetSymbolAddress(&pcw_, g_cw);
    cudaGetSymbolAddress(&pa_, g_a);
    cudaGetSymbolAddress(&px_, g_x);
    cudaGetSymbolAddress(&pact_, g_act);
    float* p_q   = (float*)pq_;
    float* p_qw  = (float*)pqw_;
    float* p_cw  = (float*)pcw_;
    float* p_a   = (float*)pa_;
    float* p_x   = (float*)px_;
    float* p_act = (float*)pact_;

    cudaFuncSetAttribute(edge_mma_kernel,
                         cudaFuncAttributeMaxDynamicSharedMemorySize, EDGE_SMEM);
    cudaFuncSetAttribute(hgemm_kernel<true, true, false>,
                         cudaFuncAttributeMaxDynamicSharedMemorySize, EDGE_SMEM);
    cudaFuncSetAttribute(hgemm_kernel<false, false, false>,
                         cudaFuncAttributeMaxDynamicSharedMemorySize, EDGE_SMEM);
    cudaFuncSetAttribute(hgemm_kernel<true, true, true>,
                         cudaFuncAttributeMaxDynamicSharedMemorySize, EDGE_SMEM);

    const int DD = D * D;
    for (int i = 0; i < NB; i++) {
        const float* cur = (i == 0) ? actors : p_act;
        float* nxt = (i == NB - 1) ? outp : p_act;
        const float* Wc0 = ctx0_W + (size_t)i * D * 3 * D;

        // q = relu(GN(actors @ Wq^T))
        hgemm_kernel<true, true, false><<<NA / MT, NT, EDGE_SMEM>>>(
            cur, query_W + i * DD, 128, query_g + i * D, query_b + i * D, nullptr, p_q);
        // qW = q @ Wc0[:,128:256]^T
        hgemm_kernel<false, false, false><<<NA / MT, NT, EDGE_SMEM>>>(
            p_q, Wc0 + 128, 384, nullptr, nullptr, nullptr, p_qw);
        // cW = nodes @ Wc0[:,256:384]^T
        hgemm_kernel<false, false, false><<<NN / MT, NT, EDGE_SMEM>>>(
            nodes, Wc0 + 256, 384, nullptr, nullptr, nullptr, p_cw);
        // a = actors @ Wagt^T
        hgemm_kernel<false, false, false><<<NA / MT, NT, EDGE_SMEM>>>(
            cur, agt_W + i * DD, 128, nullptr, nullptr, nullptr, p_a);
        // fused edge chain (HMMA) + scatter into a
        edge_mma_kernel<<<NE / MT, NT, EDGE_SMEM>>>(
            actor_ctrs, node_ctrs, hi, wi,
            dist0_W + i * D * 2, dist0_b + i * D,
            dist1_W + i * DD, dist1_g + i * D, dist1_b + i * D,
            Wc0, ctx0_g + i * D, ctx0_b + i * D,
            ctx1_W + i * DD);
        // x = relu(GN(a))
        gnrows_kernel<<<NA / 8, 256>>>(p_a, norm_g + i * D, norm_b + i * D, p_x);
        // out = relu(GN(x @ Wlin^T) + res)
        hgemm_kernel<true, true, true><<<NA / MT, NT, EDGE_SMEM>>>(
            p_x, lin_W + i * DD, 128, lin_g + i * D, lin_b + i * D, cur, nxt);
    }
}